// round 2
// baseline (speedup 1.0000x reference)
#include <cuda_runtime.h>
#include <cuda_bf16.h>
#include <math.h>

// ---------------------------------------------------------------- dims
#define Dd 512
#define Hh 512
#define Ff 2048
#define Ll 2
#define Ss 4
#define Pp 2
#define Tt 3
#define Ee 10
#define NEe 6
#define Gg 64
#define Bb 4096
#define NG 18   // T * NE groups

// ---------------------------------------------------------------- scratch (device globals; no allocs allowed)
__device__ float g_h [(size_t)NG * Bb * Hh];   // 144 MB  running hidden state
__device__ float g_t1[(size_t)NG * Bb * Hh];   // 144 MB
__device__ float g_t2[(size_t)NG * Bb * Hh];   // 144 MB
__device__ float g_f [(size_t)NG * Bb * Ff];   // 576 MB  FFN intermediate
__device__ float g_o [(size_t)NG * Bb * Hh];   // 144 MB  expert outputs
__device__ float g_gh  [(size_t)Tt * Bb * Gg];
__device__ float g_gate[(size_t)Tt * Bb * NEe];
__device__ float g_cat [(size_t)Bb * Tt * Dd];
__device__ float g_fuse[(size_t)Bb * 2 * Dd];

// ---------------------------------------------------------------- f32x2 packed helpers (full-rate fp32 on sm_103a)
__device__ __forceinline__ unsigned long long pack2(float lo, float hi) {
    unsigned long long r;
    asm("mov.b64 %0, {%1, %2};" : "=l"(r) : "f"(lo), "f"(hi));
    return r;
}
__device__ __forceinline__ void fma2(unsigned long long& d, unsigned long long a, unsigned long long b) {
    asm("fma.rn.f32x2 %0, %1, %2, %3;" : "=l"(d) : "l"(a), "l"(b), "l"(d));
}
__device__ __forceinline__ float2 unpack2(unsigned long long v) {
    float2 r;
    asm("mov.b64 {%0, %1}, %2;" : "=f"(r.x), "=f"(r.y) : "l"(v));
    return r;
}

__device__ __forceinline__ float warp_sum(float v) {
    v += __shfl_xor_sync(0xffffffffu, v, 16);
    v += __shfl_xor_sync(0xffffffffu, v, 8);
    v += __shfl_xor_sync(0xffffffffu, v, 4);
    v += __shfl_xor_sync(0xffffffffu, v, 2);
    v += __shfl_xor_sync(0xffffffffu, v, 1);
    return v;
}

__device__ __forceinline__ int expert_of_group(int g) {
    int task = g / NEe;
    int n = g % NEe;
    return (n < Ss) ? n : Ss + task * Pp + (n - Ss);
}

// ---------------------------------------------------------------- generic grouped GEMM
// C[g] = epi( A[g] @ W[expert(g)] + bias[expert(g)] (+ Res[g]) )
// A row-major [M,K], W row-major [K,N], C row-major [M,N].
// aMode/resMode: 0 -> offset 0, 1 -> (g/NE)*stride (by task), 2 -> g*stride.
// wMode: 0 -> index 0, 1 -> expert_of_group(g), 2 -> g.
// EPI: 0 none, 1 exact gelu, 2 relu
#define BM 128
#define BN 128
#define BKK 8

template <int EPI>
__global__ __launch_bounds__(256, 2)
void gemm_kernel(const float* __restrict__ A, long aStride, int aMode,
                 const float* __restrict__ W, long wStride, int wMode,
                 const float* __restrict__ bias, long bStride,
                 const float* __restrict__ Res, long resStride, int resMode,
                 float* __restrict__ C, long cStride,
                 int M, int N, int K)
{
    const int g    = blockIdx.z;
    const int task = g / NEe;
    int widx = 0;
    if (wMode == 1) widx = expert_of_group(g);
    else if (wMode == 2) widx = g;
    long aoff = 0;
    if (aMode == 1) aoff = (long)task * aStride;
    else if (aMode == 2) aoff = (long)g * aStride;

    const float* Ag = A + aoff;
    const float* Wg = W + (long)widx * wStride;
    const float* Bg = bias ? bias + (long)widx * bStride : nullptr;

    __shared__ float As[BKK][BM];
    __shared__ float Bs[BKK][BN];

    const int tid  = threadIdx.x;
    const int warp = tid >> 5;
    const int lane = tid & 31;
    // warp tiling: 4x2 warps of 32x64; lane -> 4x8 grid of 8x8 tiles
    const int rowC = (warp >> 1) * 32 + (lane >> 3) * 8;
    const int colC = (warp & 1) * 64 + (lane & 7) * 8;

    const int blockRow = blockIdx.y * BM;
    const int blockCol = blockIdx.x * BN;

    // global->shared mapping
    const int arow = tid >> 1;          // 0..127
    const int acol = (tid & 1) * 4;     // 0 or 4
    const int brow = tid >> 5;          // 0..7
    const int bcol = (lane) * 4;        // 0..124

    unsigned long long acc[8][4];
#pragma unroll
    for (int i = 0; i < 8; i++)
#pragma unroll
        for (int j = 0; j < 4; j++) acc[i][j] = 0ULL;

    const float* Aptr = Ag + (long)(blockRow + arow) * K + acol;
    const float* Wptr = Wg + (long)brow * N + blockCol + bcol;
    const bool bLoadOk = (blockCol + bcol) < N;

    for (int kt = 0; kt < K; kt += BKK) {
        float4 av = *(const float4*)Aptr;
        Aptr += BKK;
        float4 bv = make_float4(0.f, 0.f, 0.f, 0.f);
        if (bLoadOk) bv = *(const float4*)Wptr;
        Wptr += (long)BKK * N;

        As[acol + 0][arow] = av.x;
        As[acol + 1][arow] = av.y;
        As[acol + 2][arow] = av.z;
        As[acol + 3][arow] = av.w;
        *(float4*)&Bs[brow][bcol] = bv;
        __syncthreads();

#pragma unroll
        for (int k = 0; k < BKK; k++) {
            float4 a0 = *(const float4*)&As[k][rowC];
            float4 a1 = *(const float4*)&As[k][rowC + 4];
            float4 b0 = *(const float4*)&Bs[k][colC];
            float4 b1 = *(const float4*)&Bs[k][colC + 4];
            unsigned long long bb[4] = { pack2(b0.x, b0.y), pack2(b0.z, b0.w),
                                         pack2(b1.x, b1.y), pack2(b1.z, b1.w) };
            float a[8] = { a0.x, a0.y, a0.z, a0.w, a1.x, a1.y, a1.z, a1.w };
#pragma unroll
            for (int i = 0; i < 8; i++) {
                unsigned long long aa = pack2(a[i], a[i]);
#pragma unroll
                for (int j = 0; j < 4; j++) fma2(acc[i][j], aa, bb[j]);
            }
        }
        __syncthreads();
    }

    // ---------------- epilogue
    const int ccol = blockCol + colC;
    if (ccol >= N) return;   // N is a multiple of 8; whole 8-col chunk in/out

    float bvals[8];
    if (Bg) {
        float4 q0 = *(const float4*)(Bg + ccol);
        float4 q1 = *(const float4*)(Bg + ccol + 4);
        bvals[0] = q0.x; bvals[1] = q0.y; bvals[2] = q0.z; bvals[3] = q0.w;
        bvals[4] = q1.x; bvals[5] = q1.y; bvals[6] = q1.z; bvals[7] = q1.w;
    } else {
#pragma unroll
        for (int j = 0; j < 8; j++) bvals[j] = 0.f;
    }

    float* Cp = C + (long)g * cStride + (long)(blockRow + rowC) * N + ccol;
    const float* Rp = nullptr;
    if (Res) {
        long roff = (resMode == 1) ? (long)task * resStride : (long)g * resStride;
        Rp = Res + roff + (long)(blockRow + rowC) * N + ccol;
    }

#pragma unroll
    for (int i = 0; i < 8; i++) {
        float v[8];
#pragma unroll
        for (int j = 0; j < 4; j++) {
            float2 p = unpack2(acc[i][j]);
            v[2 * j]     = p.x + bvals[2 * j];
            v[2 * j + 1] = p.y + bvals[2 * j + 1];
        }
        if (Rp) {
            float4 r0 = *(const float4*)(Rp + (long)i * N);
            float4 r1 = *(const float4*)(Rp + (long)i * N + 4);
            v[0] += r0.x; v[1] += r0.y; v[2] += r0.z; v[3] += r0.w;
            v[4] += r1.x; v[5] += r1.y; v[6] += r1.z; v[7] += r1.w;
        }
        if (EPI == 1) {
#pragma unroll
            for (int j = 0; j < 8; j++)
                v[j] = 0.5f * v[j] * (1.0f + erff(v[j] * 0.70710678118654752440f));
        } else if (EPI == 2) {
#pragma unroll
            for (int j = 0; j < 8; j++) v[j] = fmaxf(v[j], 0.f);
        }
        float4 s0 = make_float4(v[0], v[1], v[2], v[3]);
        float4 s1 = make_float4(v[4], v[5], v[6], v[7]);
        *(float4*)(Cp + (long)i * N)     = s0;
        *(float4*)(Cp + (long)i * N + 4) = s1;
    }
}

// ---------------------------------------------------------------- fused LayerNorm: H = LN(H + Add) * gamma + beta
// grid: (Bb rows, NG groups), 128 threads, 4 elems each (Hdim = 512 fixed)
__global__ void ln_kernel(float* __restrict__ Hbuf, const float* __restrict__ Add,
                          const float* __restrict__ gamma, const float* __restrict__ beta,
                          long gStride)
{
    const int g   = blockIdx.y;
    const int row = blockIdx.x;
    const int e   = expert_of_group(g);
    const long off = ((long)g * Bb + row) * Hh;
    float* h = Hbuf + off;
    const int t = threadIdx.x;

    float4 hv = *(const float4*)&h[t * 4];
    if (Add) {
        float4 av = *(const float4*)&Add[off + t * 4];
        hv.x += av.x; hv.y += av.y; hv.z += av.z; hv.w += av.w;
    }
    float s = hv.x + hv.y + hv.z + hv.w;
    __shared__ float sh[8];
    const int wid = t >> 5, lane = t & 31;
    s = warp_sum(s);
    if (lane == 0) sh[wid] = s;
    __syncthreads();
    float tot = sh[0] + sh[1] + sh[2] + sh[3];
    float mean = tot * (1.0f / Hh);

    float d0 = hv.x - mean, d1 = hv.y - mean, d2 = hv.z - mean, d3 = hv.w - mean;
    float ss = d0 * d0 + d1 * d1 + d2 * d2 + d3 * d3;
    ss = warp_sum(ss);
    if (lane == 0) sh[4 + wid] = ss;
    __syncthreads();
    float var = (sh[4] + sh[5] + sh[6] + sh[7]) * (1.0f / Hh);
    float inv = rsqrtf(var + 1e-5f);

    const float* gm = gamma + (long)e * gStride;
    const float* bt = beta  + (long)e * gStride;
    float4 gv = *(const float4*)&gm[t * 4];
    float4 bv = *(const float4*)&bt[t * 4];
    float4 outv;
    outv.x = d0 * inv * gv.x + bv.x;
    outv.y = d1 * inv * gv.y + bv.y;
    outv.z = d2 * inv * gv.z + bv.z;
    outv.w = d3 * inv * gv.w + bv.w;
    *(float4*)&h[t * 4] = outv;
}

// ---------------------------------------------------------------- gate stage 2: logits = gh @ Wg2 + bg2, softmax
// one warp per (task,row); grid (Bb/4, Tt), 128 threads
__global__ void gate2_kernel(const float* __restrict__ gh, const float* __restrict__ Wg2,
                             const float* __restrict__ bg2, float* __restrict__ gate)
{
    const int i    = blockIdx.y;
    const int row  = blockIdx.x * 4 + (threadIdx.x >> 5);
    const int lane = threadIdx.x & 31;
    const float* g1 = gh + ((long)i * Bb + row) * Gg;
    const float  x0 = g1[lane];
    const float  x1 = g1[lane + 32];
    const float* w  = Wg2 + (long)i * Gg * NEe;

    float logits[NEe];
#pragma unroll
    for (int n = 0; n < NEe; n++) {
        float p = x0 * w[lane * NEe + n] + x1 * w[(lane + 32) * NEe + n];
        p = warp_sum(p);
        logits[n] = p + bg2[i * NEe + n];
    }
    float m = logits[0];
#pragma unroll
    for (int n = 1; n < NEe; n++) m = fmaxf(m, logits[n]);
    float ssum = 0.f;
#pragma unroll
    for (int n = 0; n < NEe; n++) { logits[n] = expf(logits[n] - m); ssum += logits[n]; }
    float rs = 1.0f / ssum;
    if (lane == 0) {
        float* gp = gate + ((long)i * Bb + row) * NEe;
#pragma unroll
        for (int n = 0; n < NEe; n++) gp[n] = logits[n] * rs;
    }
}

// ---------------------------------------------------------------- gated combine: cat[b, i*D+d] = sum_n o[i*6+n,b,d]*g[i,b,n]
__global__ void combine_kernel(const float* __restrict__ o, const float* __restrict__ gate,
                               float* __restrict__ cat)
{
    long idx = (long)blockIdx.x * blockDim.x + threadIdx.x;   // over Tt*Bb*Dd
    int d = (int)(idx % Dd);
    long bi = idx / Dd;
    int b = (int)(bi % Bb);
    int i = (int)(bi / Bb);
    const float* gp = gate + ((long)i * Bb + b) * NEe;
    float s = 0.f;
#pragma unroll
    for (int n = 0; n < NEe; n++)
        s += o[(((long)(i * NEe + n)) * Bb + b) * Hh + d] * gp[n];
    cat[(long)b * (Tt * Dd) + i * Dd + d] = s;
}

// ---------------------------------------------------------------- launch
extern "C" void kernel_launch(void* const* d_in, const int* in_sizes, int n_in,
                              void* d_out, int out_size)
{
    const float* x    = (const float*)d_in[0];
    const float* Win  = (const float*)d_in[1];
    const float* b_in = (const float*)d_in[2];
    const float* Wv   = (const float*)d_in[3];
    const float* bv   = (const float*)d_in[4];
    const float* Wo   = (const float*)d_in[5];
    const float* bo   = (const float*)d_in[6];
    const float* ln1g = (const float*)d_in[7];
    const float* ln1b = (const float*)d_in[8];
    const float* W1   = (const float*)d_in[9];
    const float* b1   = (const float*)d_in[10];
    const float* W2   = (const float*)d_in[11];
    const float* b2   = (const float*)d_in[12];
    const float* ln2g = (const float*)d_in[13];
    const float* ln2b = (const float*)d_in[14];
    const float* lnfg = (const float*)d_in[15];
    const float* lnfb = (const float*)d_in[16];
    const float* Wout = (const float*)d_in[17];
    const float* bout = (const float*)d_in[18];
    const float* Wg1  = (const float*)d_in[19];
    const float* bg1  = (const float*)d_in[20];
    const float* Wg2  = (const float*)d_in[21];
    const float* bg2  = (const float*)d_in[22];
    const float* Wf1  = (const float*)d_in[23];
    const float* bf1  = (const float*)d_in[24];
    const float* Wf2  = (const float*)d_in[25];
    const float* bf2  = (const float*)d_in[26];

    float *h, *t1, *t2, *f, *o, *gh, *gate, *cat, *fuse;
    cudaGetSymbolAddress((void**)&h,    g_h);
    cudaGetSymbolAddress((void**)&t1,   g_t1);
    cudaGetSymbolAddress((void**)&t2,   g_t2);
    cudaGetSymbolAddress((void**)&f,    g_f);
    cudaGetSymbolAddress((void**)&o,    g_o);
    cudaGetSymbolAddress((void**)&gh,   g_gh);
    cudaGetSymbolAddress((void**)&gate, g_gate);
    cudaGetSymbolAddress((void**)&cat,  g_cat);
    cudaGetSymbolAddress((void**)&fuse, g_fuse);

    const long GB = (long)Bb * Hh;   // per-group hidden stride
    const long GF = (long)Bb * Ff;

    dim3 blk(256);
    dim3 gHH(Hh / BN, Bb / BM, NG);   // (4, 32, 18)
    dim3 gHF(Ff / BN, Bb / BM, NG);   // (16, 32, 18)
    dim3 lnG(Bb, NG);

    // 1. input projection: h = x[task] @ Win[e] + b_in[e]
    gemm_kernel<0><<<gHH, blk>>>(x, (long)Bb * Dd, 1,
                                 Win, (long)Dd * Hh, 1, b_in, Hh,
                                 nullptr, 0, 0, h, GB, Bb, Hh, Dd);

    for (int l = 0; l < Ll; l++) {
        // v = h @ Wv + bv
        gemm_kernel<0><<<gHH, blk>>>(h, GB, 2,
                                     Wv + (long)l * Hh * Hh, (long)Ll * Hh * Hh, 1,
                                     bv + (long)l * Hh, (long)Ll * Hh,
                                     nullptr, 0, 0, t1, GB, Bb, Hh, Hh);
        // a = v @ Wo + bo
        gemm_kernel<0><<<gHH, blk>>>(t1, GB, 2,
                                     Wo + (long)l * Hh * Hh, (long)Ll * Hh * Hh, 1,
                                     bo + (long)l * Hh, (long)Ll * Hh,
                                     nullptr, 0, 0, t2, GB, Bb, Hh, Hh);
        // h = LN(h + a)
        ln_kernel<<<lnG, 128>>>(h, t2, ln1g + (long)l * Hh, ln1b + (long)l * Hh, (long)Ll * Hh);
        // f = gelu(h @ W1 + b1)
        gemm_kernel<1><<<gHF, blk>>>(h, GB, 2,
                                     W1 + (long)l * Hh * Ff, (long)Ll * Hh * Ff, 1,
                                     b1 + (long)l * Ff, (long)Ll * Ff,
                                     nullptr, 0, 0, f, GF, Bb, Ff, Hh);
        // t1 = f @ W2 + b2
        gemm_kernel<0><<<gHH, blk>>>(f, GF, 2,
                                     W2 + (long)l * Ff * Hh, (long)Ll * Ff * Hh, 1,
                                     b2 + (long)l * Hh, (long)Ll * Hh,
                                     nullptr, 0, 0, t1, GB, Bb, Hh, Ff);
        // h = LN(h + t1)
        ln_kernel<<<lnG, 128>>>(h, t1, ln2g + (long)l * Hh, ln2b + (long)l * Hh, (long)Ll * Hh);
    }

    // final norm
    ln_kernel<<<lnG, 128>>>(h, nullptr, lnfg, lnfb, (long)Hh);

    // o = h @ Wout + bout + x[task]
    gemm_kernel<0><<<gHH, blk>>>(h, GB, 2,
                                 Wout, (long)Hh * Dd, 1, bout, Dd,
                                 x, (long)Bb * Dd, 1, o, GB, Bb, Dd, Hh);

    // gate stage 1: gh = relu(x[i] @ Wg1[i] + bg1[i])
    gemm_kernel<2><<<dim3(1, Bb / BM, Tt), blk>>>(x, (long)Bb * Dd, 2,
                                                  Wg1, (long)Dd * Gg, 2, bg1, Gg,
                                                  nullptr, 0, 0, gh, (long)Bb * Gg,
                                                  Bb, Gg, Dd);
    // gate stage 2 + softmax
    gate2_kernel<<<dim3(Bb / 4, Tt), 128>>>(gh, Wg2, bg2, gate);

    // gated combine -> cat
    combine_kernel<<<(Tt * Bb * Dd) / 256, 256>>>(o, gate, cat);

    // fusion MLP
    gemm_kernel<2><<<dim3((2 * Dd) / BN, Bb / BM, 1), blk>>>(cat, 0, 0,
                                                             Wf1, 0, 0, bf1, 0,
                                                             nullptr, 0, 0, fuse, 0,
                                                             Bb, 2 * Dd, Tt * Dd);
    gemm_kernel<0><<<dim3(Dd / BN, Bb / BM, 1), blk>>>(fuse, 0, 0,
                                                       Wf2, 0, 0, bf2, 0,
                                                       nullptr, 0, 0, (float*)d_out, 0,
                                                       Bb, Dd, 2 * Dd);
}

// round 4
// speedup vs baseline: 2.3138x; 2.3138x over previous
#include <cuda_runtime.h>
#include <cuda_bf16.h>
#include <math.h>
#include <stdint.h>

#define Dd 512
#define Hh 512
#define Ff 2048
#define Ll 2
#define Ss 4
#define Pp 2
#define Tt 3
#define NEe 6
#define Gg 64
#define Bb 4096
#define NG 18

typedef __nv_bfloat16 bf16;

// ---------------- scratch (device globals; allocation-free)
__device__ __align__(16) bf16 g_wWin_h [2621440],  g_wWin_l [2621440];
__device__ __align__(16) bf16 g_wWv_h  [5242880],  g_wWv_l  [5242880];
__device__ __align__(16) bf16 g_wWo_h  [5242880],  g_wWo_l  [5242880];
__device__ __align__(16) bf16 g_wW1_h  [20971520], g_wW1_l  [20971520];
__device__ __align__(16) bf16 g_wW2_h  [20971520], g_wW2_l  [20971520];
__device__ __align__(16) bf16 g_wWout_h[2621440],  g_wWout_l[2621440];
__device__ __align__(16) bf16 g_wWf1_h [1572864],  g_wWf1_l [1572864];
__device__ __align__(16) bf16 g_wWf2_h [524288],   g_wWf2_l [524288];
__device__ __align__(16) bf16 g_x_h [6291456],   g_x_l [6291456];
__device__ float g_h32 [37748736];
__device__ __align__(16) bf16 g_h_h [37748736],  g_h_l [37748736];
__device__ __align__(16) bf16 g_t1_h[37748736],  g_t1_l[37748736];
__device__ float g_t232[37748736];
__device__ __align__(16) bf16 g_f_h [150994944], g_f_l [150994944];
__device__ float g_o32 [37748736];
__device__ float g_gh  [(size_t)Tt * Bb * Gg];
__device__ float g_gate[(size_t)Tt * Bb * NEe];
__device__ __align__(16) bf16 g_cat_h [6291456], g_cat_l [6291456];
__device__ __align__(16) bf16 g_fuse_h[4194304], g_fuse_l[4194304];

// ---------------- helpers
__device__ __forceinline__ void cp16(void* dst, const void* src) {
    uint32_t d;
    asm("{ .reg .u64 t; cvta.to.shared.u64 t, %1; cvt.u32.u64 %0, t; }" : "=r"(d) : "l"(dst));
    asm volatile("cp.async.cg.shared.global [%0], [%1], 16;" :: "r"(d), "l"(src) : "memory");
}
__device__ __forceinline__ void mma_bf16(float* c, const uint32_t* a, const uint32_t* b) {
    asm volatile("mma.sync.aligned.m16n8k16.row.col.f32.bf16.bf16.f32 "
                 "{%0,%1,%2,%3}, {%4,%5,%6,%7}, {%8,%9}, {%0,%1,%2,%3};"
                 : "+f"(c[0]), "+f"(c[1]), "+f"(c[2]), "+f"(c[3])
                 : "r"(a[0]), "r"(a[1]), "r"(a[2]), "r"(a[3]), "r"(b[0]), "r"(b[1]));
}
__device__ __forceinline__ float warp_sum(float v) {
    v += __shfl_xor_sync(0xffffffffu, v, 16);
    v += __shfl_xor_sync(0xffffffffu, v, 8);
    v += __shfl_xor_sync(0xffffffffu, v, 4);
    v += __shfl_xor_sync(0xffffffffu, v, 2);
    v += __shfl_xor_sync(0xffffffffu, v, 1);
    return v;
}
__device__ __forceinline__ int expert_of_group(int g) {
    int task = g / NEe;
    int n = g % NEe;
    return (n < Ss) ? n : Ss + task * Pp + (n - Ss);
}

// ---------------- bf16x3 HMMA grouped GEMM
// A planes [*,K] row-major; W planes [N,K] (pre-transposed). 128x128 tile, BK=32.
// smem stage: Ah,Al,Bh,Bl each 128 rows x 40 halves (pad) = 10240B -> 40960B/stage, 2 stages.
#define ROWP 40
#define PLANE_B 10240
#define STAGE_B 40960
#define TG_SMEM (2 * STAGE_B)

template <int EPI, int OUT>   // EPI: 0 none, 1 gelu, 2 relu.  OUT: 0 f32, 1 planes, 2 both
__global__ __launch_bounds__(256)
void tgemm_kernel(const bf16* __restrict__ Ahi, const bf16* __restrict__ Alo, long aStride, int aMode,
                  const bf16* __restrict__ Whi, const bf16* __restrict__ Wlo, long wStride,
                  int wMode, int wMul, int wOff,
                  const float* __restrict__ bias, long bStride,
                  const float* __restrict__ Res, long resStride, int resMode,
                  float* __restrict__ C32, bf16* __restrict__ Chi, bf16* __restrict__ Clo,
                  long cStride, int N, int K)
{
    extern __shared__ char dsm[];

    const int g    = blockIdx.z;
    const int task = g / NEe;
    int wb = 0;
    if (wMode == 1) wb = expert_of_group(g);
    else if (wMode == 2) wb = g;
    const int widx = wb * wMul + wOff;
    const long aoff = (aMode == 1) ? (long)task * aStride : (aMode == 2 ? (long)g * aStride : 0);

    const int tid = threadIdx.x;
    const int blockRow = blockIdx.y * 128;
    const int blockCol = blockIdx.x * 128;

    const bf16* aH = Ahi + aoff + (size_t)blockRow * K;
    const bf16* aL = Alo + aoff + (size_t)blockRow * K;
    const bf16* bH = Whi + (size_t)widx * wStride + (size_t)blockCol * K;
    const bf16* bL = Wlo + (size_t)widx * wStride + (size_t)blockCol * K;

    const int warp  = tid >> 5, lane = tid & 31;
    const int warpM = warp >> 2, warpN = warp & 3;     // 2 x 4 warp grid
    const int grp   = lane >> 2, qp = lane & 3;

    // global->smem mapping: thread covers 2 rows (r, r+64), 16B seg each
    const int lrow = tid >> 2;        // 0..63
    const int lseg = tid & 3;         // 16B segment (8 halves)

    const int nch = K >> 5;           // chunks of BK=32

    auto load_chunk = [&](int kc, int s) {
        char* sb = dsm + s * STAGE_B;
        size_t kofs = (size_t)kc * 32 + (size_t)lseg * 8;
#pragma unroll
        for (int it = 0; it < 2; ++it) {
            int row = lrow + it * 64;
            size_t go = (size_t)row * K + kofs;
            size_t so = (size_t)row * (ROWP * 2) + lseg * 16;
            cp16(sb +             so, aH + go);
            cp16(sb + PLANE_B   + so, aL + go);
            cp16(sb + 2*PLANE_B + so, bH + go);
            cp16(sb + 3*PLANE_B + so, bL + go);
        }
        asm volatile("cp.async.commit_group;" ::: "memory");
    };

    float acc[4][4][4];
#pragma unroll
    for (int i = 0; i < 4; i++)
#pragma unroll
        for (int j = 0; j < 4; j++)
#pragma unroll
            for (int k = 0; k < 4; k++) acc[i][j][k] = 0.f;

    load_chunk(0, 0);
    load_chunk(1, 1);

    for (int c = 0; c < nch; ++c) {
        if (c + 2 < nch) asm volatile("cp.async.wait_group 1;" ::: "memory");
        else             asm volatile("cp.async.wait_group 0;" ::: "memory");
        __syncthreads();

        const char* sb = dsm + (c & 1) * STAGE_B;
        const char* sAh = sb;
        const char* sAl = sb + PLANE_B;
        const char* sBh = sb + 2*PLANE_B;
        const char* sBl = sb + 3*PLANE_B;

#pragma unroll
        for (int kt = 0; kt < 2; ++kt) {
            const int kb = kt * 16;
            uint32_t Af[4][4], Alf[4][4], Bf[4][2], Blf[4][2];
#pragma unroll
            for (int mt = 0; mt < 4; ++mt) {
                int r0 = warpM * 64 + mt * 16 + grp;
                size_t o00 = (size_t)r0 * (ROWP*2) + (kb + 2*qp) * 2;
                size_t o10 = o00 + 8 * (ROWP*2);
                Af[mt][0] = *(const uint32_t*)(sAh + o00);
                Af[mt][1] = *(const uint32_t*)(sAh + o10);
                Af[mt][2] = *(const uint32_t*)(sAh + o00 + 16);
                Af[mt][3] = *(const uint32_t*)(sAh + o10 + 16);
                Alf[mt][0] = *(const uint32_t*)(sAl + o00);
                Alf[mt][1] = *(const uint32_t*)(sAl + o10);
                Alf[mt][2] = *(const uint32_t*)(sAl + o00 + 16);
                Alf[mt][3] = *(const uint32_t*)(sAl + o10 + 16);
            }
#pragma unroll
            for (int nt = 0; nt < 4; ++nt) {
                int n0 = warpN * 32 + nt * 8 + grp;
                size_t o = (size_t)n0 * (ROWP*2) + (kb + 2*qp) * 2;
                Bf[nt][0] = *(const uint32_t*)(sBh + o);
                Bf[nt][1] = *(const uint32_t*)(sBh + o + 16);
                Blf[nt][0] = *(const uint32_t*)(sBl + o);
                Blf[nt][1] = *(const uint32_t*)(sBl + o + 16);
            }
#pragma unroll
            for (int mt = 0; mt < 4; ++mt)
#pragma unroll
                for (int nt = 0; nt < 4; ++nt) {
                    mma_bf16(acc[mt][nt], Af[mt], Bf[nt]);
                    mma_bf16(acc[mt][nt], Af[mt], Blf[nt]);
                    mma_bf16(acc[mt][nt], Alf[mt], Bf[nt]);
                }
        }
        __syncthreads();
        if (c + 2 < nch) load_chunk(c + 2, c & 1);
    }

    // ---- epilogue: regs -> smem f32 bounce -> coalesced gmem
    float* sbuf = reinterpret_cast<float*>(dsm);
#pragma unroll
    for (int mt = 0; mt < 4; ++mt) {
        int r0 = warpM * 64 + mt * 16 + grp;
#pragma unroll
        for (int nt = 0; nt < 4; ++nt) {
            int cb = warpN * 32 + nt * 8 + 2 * qp;
            sbuf[r0 * 129 + cb]       = acc[mt][nt][0];
            sbuf[r0 * 129 + cb + 1]   = acc[mt][nt][1];
            sbuf[(r0+8) * 129 + cb]   = acc[mt][nt][2];
            sbuf[(r0+8) * 129 + cb+1] = acc[mt][nt][3];
        }
    }
    __syncthreads();

    const size_t coff = (size_t)g * cStride;
    const size_t roff = Res ? ((resMode == 1) ? (size_t)task * resStride : (size_t)g * resStride) : 0;

#pragma unroll 4
    for (int it = 0; it < 64; ++it) {
        int idx = it * 256 + tid;
        int rr = idx >> 7, cc = idx & 127;
        int gcol = blockCol + cc;
        float v = sbuf[rr * 129 + cc];
        if (bias) v += bias[(size_t)widx * bStride + gcol];
        size_t rowoff = (size_t)(blockRow + rr) * N + gcol;
        if (Res) v += Res[roff + rowoff];
        if (EPI == 1)      v = 0.5f * v * (1.0f + erff(v * 0.70710678118654752440f));
        else if (EPI == 2) v = fmaxf(v, 0.f);
        size_t o = coff + rowoff;
        if (OUT != 1) C32[o] = v;
        if (OUT >= 1) {
            bf16 hv = __float2bfloat16(v);
            Chi[o] = hv;
            Clo[o] = __float2bfloat16(v - __bfloat162float(hv));
        }
    }
}

// ---------------- weight convert+transpose: f32 [K,N] -> bf16 hi/lo [N,K]
__global__ void wconv_kernel(const float* __restrict__ src, bf16* __restrict__ hi,
                             bf16* __restrict__ lo, int K, int N)
{
    __shared__ float tile[32][33];
    const size_t m = (size_t)blockIdx.z * K * N;
    const int n0 = blockIdx.x * 32, k0 = blockIdx.y * 32;
    const int tx = threadIdx.x, ty = threadIdx.y;
    for (int r = ty; r < 32; r += 8)
        tile[r][tx] = src[m + (size_t)(k0 + r) * N + n0 + tx];
    __syncthreads();
    for (int r = ty; r < 32; r += 8) {
        float v = tile[tx][r];
        size_t o = m + (size_t)(n0 + r) * K + k0 + tx;
        bf16 h = __float2bfloat16(v);
        hi[o] = h;
        lo[o] = __float2bfloat16(v - __bfloat162float(h));
    }
}

// ---------------- elementwise f32 -> bf16 hi/lo
__global__ void split_kernel(const float* __restrict__ src, bf16* __restrict__ hi,
                             bf16* __restrict__ lo, long n)
{
    long i = (long)blockIdx.x * blockDim.x + threadIdx.x;
    if (i < n) {
        float v = src[i];
        bf16 h = __float2bfloat16(v);
        hi[i] = h;
        lo[i] = __float2bfloat16(v - __bfloat162float(h));
    }
}

// ---------------- fused LayerNorm; writes f32 + bf16 hi/lo planes
__global__ void ln_kernel(float* __restrict__ Hbuf, bf16* __restrict__ Hhi, bf16* __restrict__ Hlo,
                          const float* __restrict__ Add,
                          const float* __restrict__ gamma, const float* __restrict__ beta, long gStride)
{
    const int g = blockIdx.y, row = blockIdx.x;
    const int e = expert_of_group(g);
    const long off = ((long)g * Bb + row) * Hh;
    float* h = Hbuf + off;
    const int t = threadIdx.x;

    float4 hv = *(const float4*)&h[t * 4];
    if (Add) {
        float4 av = *(const float4*)&Add[off + t * 4];
        hv.x += av.x; hv.y += av.y; hv.z += av.z; hv.w += av.w;
    }
    float s = hv.x + hv.y + hv.z + hv.w;
    __shared__ float sh[8];
    const int wid = t >> 5, lane = t & 31;
    s = warp_sum(s);
    if (lane == 0) sh[wid] = s;
    __syncthreads();
    float mean = (sh[0] + sh[1] + sh[2] + sh[3]) * (1.0f / Hh);
    float d0 = hv.x - mean, d1 = hv.y - mean, d2 = hv.z - mean, d3 = hv.w - mean;
    float ss = d0 * d0 + d1 * d1 + d2 * d2 + d3 * d3;
    ss = warp_sum(ss);
    if (lane == 0) sh[4 + wid] = ss;
    __syncthreads();
    float inv = rsqrtf((sh[4] + sh[5] + sh[6] + sh[7]) * (1.0f / Hh) + 1e-5f);

    const float* gm = gamma + (long)e * gStride;
    const float* bt = beta  + (long)e * gStride;
    float4 gv = *(const float4*)&gm[t * 4];
    float4 bv = *(const float4*)&bt[t * 4];
    float o0 = d0 * inv * gv.x + bv.x;
    float o1 = d1 * inv * gv.y + bv.y;
    float o2 = d2 * inv * gv.z + bv.z;
    float o3 = d3 * inv * gv.w + bv.w;
    *(float4*)&h[t * 4] = make_float4(o0, o1, o2, o3);
    float vv[4] = {o0, o1, o2, o3};
#pragma unroll
    for (int j = 0; j < 4; j++) {
        bf16 hh = __float2bfloat16(vv[j]);
        Hhi[off + t * 4 + j] = hh;
        Hlo[off + t * 4 + j] = __float2bfloat16(vv[j] - __bfloat162float(hh));
    }
}

// ---------------- gate stage 1
__global__ void gate1_kernel(const float* __restrict__ x, const float* __restrict__ Wg1,
                             const float* __restrict__ bg1, float* __restrict__ gh)
{
    __shared__ float xs[Dd];
    const int i = blockIdx.y, b = blockIdx.x, t = threadIdx.x;
    const float* xr = x + ((long)i * Bb + b) * Dd;
    for (int k = t; k < Dd; k += 64) xs[k] = xr[k];
    __syncthreads();
    const float* w = Wg1 + (long)i * Dd * Gg + t;
    float s = bg1[i * Gg + t];
#pragma unroll 8
    for (int k = 0; k < Dd; ++k) s += xs[k] * w[(long)k * Gg];
    gh[((long)i * Bb + b) * Gg + t] = fmaxf(s, 0.f);
}

// ---------------- gate stage 2 + softmax
__global__ void gate2_kernel(const float* __restrict__ gh, const float* __restrict__ Wg2,
                             const float* __restrict__ bg2, float* __restrict__ gate)
{
    const int i = blockIdx.y;
    const int row = blockIdx.x * 4 + (threadIdx.x >> 5);
    const int lane = threadIdx.x & 31;
    const float* g1 = gh + ((long)i * Bb + row) * Gg;
    const float x0 = g1[lane], x1 = g1[lane + 32];
    const float* w = Wg2 + (long)i * Gg * NEe;
    float logits[NEe];
#pragma unroll
    for (int n = 0; n < NEe; n++) {
        float p = x0 * w[lane * NEe + n] + x1 * w[(lane + 32) * NEe + n];
        p = warp_sum(p);
        logits[n] = p + bg2[i * NEe + n];
    }
    float m = logits[0];
#pragma unroll
    for (int n = 1; n < NEe; n++) m = fmaxf(m, logits[n]);
    float ssum = 0.f;
#pragma unroll
    for (int n = 0; n < NEe; n++) { logits[n] = expf(logits[n] - m); ssum += logits[n]; }
    float rs = 1.0f / ssum;
    if (lane == 0) {
        float* gp = gate + ((long)i * Bb + row) * NEe;
#pragma unroll
        for (int n = 0; n < NEe; n++) gp[n] = logits[n] * rs;
    }
}

// ---------------- gated combine -> cat hi/lo planes
__global__ void combine_kernel(const float* __restrict__ o, const float* __restrict__ gate,
                               bf16* __restrict__ cath, bf16* __restrict__ catl)
{
    long idx = (long)blockIdx.x * blockDim.x + threadIdx.x;
    int d = (int)(idx % Dd);
    long bi = idx / Dd;
    int b = (int)(bi % Bb);
    int i = (int)(bi / Bb);
    const float* gp = gate + ((long)i * Bb + b) * NEe;
    float s = 0.f;
#pragma unroll
    for (int n = 0; n < NEe; n++)
        s += o[(((long)(i * NEe + n)) * Bb + b) * Hh + d] * gp[n];
    long oidx = (long)b * (Tt * Dd) + i * Dd + d;
    bf16 h = __float2bfloat16(s);
    cath[oidx] = h;
    catl[oidx] = __float2bfloat16(s - __bfloat162float(h));
}

// ---------------- launch
extern "C" void kernel_launch(void* const* d_in, const int* in_sizes, int n_in,
                              void* d_out, int out_size)
{
    const float* x    = (const float*)d_in[0];
    const float* Win  = (const float*)d_in[1];
    const float* b_in = (const float*)d_in[2];
    const float* Wv   = (const float*)d_in[3];
    const float* bv   = (const float*)d_in[4];
    const float* Wo   = (const float*)d_in[5];
    const float* bo   = (const float*)d_in[6];
    const float* ln1g = (const float*)d_in[7];
    const float* ln1b = (const float*)d_in[8];
    const float* W1   = (const float*)d_in[9];
    const float* b1   = (const float*)d_in[10];
    const float* W2   = (const float*)d_in[11];
    const float* b2   = (const float*)d_in[12];
    const float* ln2g = (const float*)d_in[13];
    const float* ln2b = (const float*)d_in[14];
    const float* lnfg = (const float*)d_in[15];
    const float* lnfb = (const float*)d_in[16];
    const float* Wout = (const float*)d_in[17];
    const float* bout = (const float*)d_in[18];
    const float* Wg1  = (const float*)d_in[19];
    const float* bg1  = (const float*)d_in[20];
    const float* Wg2  = (const float*)d_in[21];
    const float* bg2  = (const float*)d_in[22];
    const float* Wf1  = (const float*)d_in[23];
    const float* bf1  = (const float*)d_in[24];
    const float* Wf2  = (const float*)d_in[25];
    const float* bf2  = (const float*)d_in[26];

    bf16 *wWinH, *wWinL, *wWvH, *wWvL, *wWoH, *wWoL, *wW1H, *wW1L, *wW2H, *wW2L;
    bf16 *wWoutH, *wWoutL, *wWf1H, *wWf1L, *wWf2H, *wWf2L;
    bf16 *xH, *xL, *hH, *hL, *t1H, *t1L, *fH, *fL, *catH, *catL, *fuH, *fuL;
    float *h32, *t232, *o32, *gh, *gate;
    cudaGetSymbolAddress((void**)&wWinH, g_wWin_h);  cudaGetSymbolAddress((void**)&wWinL, g_wWin_l);
    cudaGetSymbolAddress((void**)&wWvH,  g_wWv_h);   cudaGetSymbolAddress((void**)&wWvL,  g_wWv_l);
    cudaGetSymbolAddress((void**)&wWoH,  g_wWo_h);   cudaGetSymbolAddress((void**)&wWoL,  g_wWo_l);
    cudaGetSymbolAddress((void**)&wW1H,  g_wW1_h);   cudaGetSymbolAddress((void**)&wW1L,  g_wW1_l);
    cudaGetSymbolAddress((void**)&wW2H,  g_wW2_h);   cudaGetSymbolAddress((void**)&wW2L,  g_wW2_l);
    cudaGetSymbolAddress((void**)&wWoutH,g_wWout_h); cudaGetSymbolAddress((void**)&wWoutL,g_wWout_l);
    cudaGetSymbolAddress((void**)&wWf1H, g_wWf1_h);  cudaGetSymbolAddress((void**)&wWf1L, g_wWf1_l);
    cudaGetSymbolAddress((void**)&wWf2H, g_wWf2_h);  cudaGetSymbolAddress((void**)&wWf2L, g_wWf2_l);
    cudaGetSymbolAddress((void**)&xH, g_x_h);   cudaGetSymbolAddress((void**)&xL, g_x_l);
    cudaGetSymbolAddress((void**)&hH, g_h_h);   cudaGetSymbolAddress((void**)&hL, g_h_l);
    cudaGetSymbolAddress((void**)&t1H, g_t1_h); cudaGetSymbolAddress((void**)&t1L, g_t1_l);
    cudaGetSymbolAddress((void**)&fH, g_f_h);   cudaGetSymbolAddress((void**)&fL, g_f_l);
    cudaGetSymbolAddress((void**)&catH, g_cat_h); cudaGetSymbolAddress((void**)&catL, g_cat_l);
    cudaGetSymbolAddress((void**)&fuH, g_fuse_h); cudaGetSymbolAddress((void**)&fuL, g_fuse_l);
    cudaGetSymbolAddress((void**)&h32, g_h32);  cudaGetSymbolAddress((void**)&t232, g_t232);
    cudaGetSymbolAddress((void**)&o32, g_o32);  cudaGetSymbolAddress((void**)&gh, g_gh);
    cudaGetSymbolAddress((void**)&gate, g_gate);

    cudaFuncSetAttribute((const void*)tgemm_kernel<0,0>, cudaFuncAttributeMaxDynamicSharedMemorySize, TG_SMEM);
    cudaFuncSetAttribute((const void*)tgemm_kernel<0,1>, cudaFuncAttributeMaxDynamicSharedMemorySize, TG_SMEM);
    cudaFuncSetAttribute((const void*)tgemm_kernel<0,2>, cudaFuncAttributeMaxDynamicSharedMemorySize, TG_SMEM);
    cudaFuncSetAttribute((const void*)tgemm_kernel<1,1>, cudaFuncAttributeMaxDynamicSharedMemorySize, TG_SMEM);
    cudaFuncSetAttribute((const void*)tgemm_kernel<2,1>, cudaFuncAttributeMaxDynamicSharedMemorySize, TG_SMEM);

    dim3 cb(32, 8);
    wconv_kernel<<<dim3(Hh/32, Dd/32, 10), cb>>>(Win,  wWinH,  wWinL,  Dd, Hh);
    wconv_kernel<<<dim3(Hh/32, Hh/32, 20), cb>>>(Wv,   wWvH,   wWvL,   Hh, Hh);
    wconv_kernel<<<dim3(Hh/32, Hh/32, 20), cb>>>(Wo,   wWoH,   wWoL,   Hh, Hh);
    wconv_kernel<<<dim3(Ff/32, Hh/32, 20), cb>>>(W1,   wW1H,   wW1L,   Hh, Ff);
    wconv_kernel<<<dim3(Hh/32, Ff/32, 20), cb>>>(W2,   wW2H,   wW2L,   Ff, Hh);
    wconv_kernel<<<dim3(Dd/32, Hh/32, 10), cb>>>(Wout, wWoutH, wWoutL, Hh, Dd);
    wconv_kernel<<<dim3((2*Dd)/32, (Tt*Dd)/32, 1), cb>>>(Wf1, wWf1H, wWf1L, Tt*Dd, 2*Dd);
    wconv_kernel<<<dim3(Dd/32, (2*Dd)/32, 1), cb>>>(Wf2, wWf2H, wWf2L, 2*Dd, Dd);

    long nx = (long)Tt * Bb * Dd;
    split_kernel<<<(unsigned)((nx + 255) / 256), 256>>>(x, xH, xL, nx);

    gate1_kernel<<<dim3(Bb, Tt), 64>>>(x, Wg1, bg1, gh);
    gate2_kernel<<<dim3(Bb / 4, Tt), 128>>>(gh, Wg2, bg2, gate);

    const long GB = (long)Bb * Hh;
    const long GF = (long)Bb * Ff;
    dim3 blk(256);
    dim3 gHH(Hh / 128, Bb / 128, NG);
    dim3 gHF(Ff / 128, Bb / 128, NG);
    dim3 lnG(Bb, NG);

    // input projection: h = x[task] @ Win[e] + b_in[e]   (f32 + planes)
    tgemm_kernel<0,2><<<gHH, blk, TG_SMEM>>>(xH, xL, (long)Bb * Dd, 1,
        wWinH, wWinL, (long)Dd * Hh, 1, 1, 0, b_in, Hh,
        nullptr, 0, 0, h32, hH, hL, GB, Hh, Dd);

    for (int l = 0; l < Ll; l++) {
        tgemm_kernel<0,1><<<gHH, blk, TG_SMEM>>>(hH, hL, GB, 2,
            wWvH, wWvL, (long)Hh * Hh, 1, Ll, l, bv, Hh,
            nullptr, 0, 0, nullptr, t1H, t1L, GB, Hh, Hh);
        tgemm_kernel<0,0><<<gHH, blk, TG_SMEM>>>(t1H, t1L, GB, 2,
            wWoH, wWoL, (long)Hh * Hh, 1, Ll, l, bo, Hh,
            nullptr, 0, 0, t232, nullptr, nullptr, GB, Hh, Hh);
        ln_kernel<<<lnG, 128>>>(h32, hH, hL, t232, ln1g + (long)l * Hh, ln1b + (long)l * Hh, (long)Ll * Hh);
        tgemm_kernel<1,1><<<gHF, blk, TG_SMEM>>>(hH, hL, GB, 2,
            wW1H, wW1L, (long)Hh * Ff, 1, Ll, l, b1, Ff,
            nullptr, 0, 0, nullptr, fH, fL, GF, Ff, Hh);
        tgemm_kernel<0,0><<<gHH, blk, TG_SMEM>>>(fH, fL, GF, 2,
            wW2H, wW2L, (long)Ff * Hh, 1, Ll, l, b2, Hh,
            nullptr, 0, 0, t232, nullptr, nullptr, GB, Hh, Ff);
        ln_kernel<<<lnG, 128>>>(h32, hH, hL, t232, ln2g + (long)l * Hh, ln2b + (long)l * Hh, (long)Ll * Hh);
    }

    ln_kernel<<<lnG, 128>>>(h32, hH, hL, nullptr, lnfg, lnfb, (long)Hh);

    tgemm_kernel<0,0><<<gHH, blk, TG_SMEM>>>(hH, hL, GB, 2,
        wWoutH, wWoutL, (long)Hh * Dd, 1, 1, 0, bout, Dd,
        x, (long)Bb * Dd, 1, o32, nullptr, nullptr, GB, Dd, Hh);

    combine_kernel<<<(unsigned)(((long)Tt * Bb * Dd) / 256), 256>>>(o32, gate, catH, catL);

    tgemm_kernel<2,1><<<dim3((2*Dd)/128, Bb/128, 1), blk, TG_SMEM>>>(catH, catL, 0, 0,
        wWf1H, wWf1L, 0, 0, 1, 0, bf1, 0,
        nullptr, 0, 0, nullptr, fuH, fuL, 0, 2*Dd, Tt*Dd);
    tgemm_kernel<0,0><<<dim3(Dd/128, Bb/128, 1), blk, TG_SMEM>>>(fuH, fuL, 0, 0,
        wWf2H, wWf2L, 0, 0, 1, 0, bf2, 0,
        nullptr, 0, 0, (float*)d_out, nullptr, nullptr, 0, Dd, 2*Dd);
}